// round 9
// baseline (speedup 1.0000x reference)
#include <cuda_runtime.h>
#include <cuda_bf16.h>
#include <cstdint>

#define NN   128
#define DD   128
#define EE   128
#define NG   8
#define VDIM 300

// ---------------- device scratch (allocation-free) ----------------
__device__ float g_base[NN * DD];
__device__ float g_vacc[NG][NN * DD];      // child-transform sums; zeroed by k_reset
__device__ float g_u[NG][NN][DD];          // path vectors, idx 0..plen-1 (idx0 = v0 w/ relu)
__device__ float g_w2[NG][DD];
__device__ float g_cconst[NG];
__device__ float g_dscore;
__device__ int   g_cnt[NG][NN];            // child-completion counters (warp granularity)
__device__ int   g_par[NG][NN];
__device__ int   g_cc[NG][NN];
__device__ unsigned char g_inpath[NG][NN];
__device__ int   g_plen[NG];
__device__ int   g_plist[NG][NN];
__device__ int   g_pedge[NG][NN];
// flags (zeroed by k_reset every launch)
__device__ int   c_parse[NG];
__device__ int   c_fold[NG];
__device__ int   c_path[NG];
__device__ int   c_base[NN];
__device__ int   c_dscore;

// =============== reset: runs first every launch; immune to dirty state ===============
__global__ void k_reset() {
    int i = blockIdx.x * blockDim.x + threadIdx.x;   // 0..32767
    ((float4*)g_vacc)[i] = make_float4(0.f, 0.f, 0.f, 0.f);   // 8*128*128/4 = 32768
    if (i < NG) { c_parse[i] = 0; c_fold[i] = 0; c_path[i] = 0; }
    if (i < NN) c_base[i] = 0;
    if (i < NG * NN) ((int*)g_cnt)[i] = 0;
    if (i == 0) c_dscore = 0;
}

// ---------------- helpers ----------------
__device__ __forceinline__ void warp_spin_ge(int* p, int tgt) {
    if ((threadIdx.x & 31) == 0) {
        while (atomicAdd(p, 0) < tgt) __nanosleep(32);
    }
    __syncwarp();
    __threadfence();
}

// y[k] += sum_d v[d] * W[d*DD + k]   (v @ W), v distributed float4/lane
__device__ __forceinline__ float4 mv_acc(const float* __restrict__ W, float4 vv, float4 y) {
    const float* Wl = W + (threadIdx.x & 31) * 4;
#pragma unroll 4
    for (int dq = 0; dq < 32; dq++) {
        float a0 = __shfl_sync(0xffffffffu, vv.x, dq);
        float a1 = __shfl_sync(0xffffffffu, vv.y, dq);
        float a2 = __shfl_sync(0xffffffffu, vv.z, dq);
        float a3 = __shfl_sync(0xffffffffu, vv.w, dq);
        float4 w0 = __ldg((const float4*)(Wl + (4 * dq + 0) * DD));
        float4 w1 = __ldg((const float4*)(Wl + (4 * dq + 1) * DD));
        float4 w2 = __ldg((const float4*)(Wl + (4 * dq + 2) * DD));
        float4 w3 = __ldg((const float4*)(Wl + (4 * dq + 3) * DD));
        y.x += a0 * w0.x + a1 * w1.x + a2 * w2.x + a3 * w3.x;
        y.y += a0 * w0.y + a1 * w1.y + a2 * w2.y + a3 * w3.y;
        y.z += a0 * w0.z + a1 * w1.z + a2 * w2.z + a3 * w3.z;
        y.w += a0 * w0.w + a1 * w1.w + a2 * w2.w + a3 * w3.w;
    }
    return y;
}

__device__ __forceinline__ float warp_red(float v) {
    for (int o = 16; o; o >>= 1) v += __shfl_xor_sync(0xffffffffu, v, o);
    return v;
}

// ---------------- the fused kernel ----------------
__global__ void __launch_bounds__(256, 1)
k_fused(const int* __restrict__ data, const int* __restrict__ graphs,
        const int* __restrict__ edges, const int* __restrict__ posp,
        const float* __restrict__ dv, const float* __restrict__ dw,
        const float* __restrict__ db, const float* __restrict__ ew,
        const float* __restrict__ ebias, const float* __restrict__ sew,
        const float* __restrict__ sdw, const float* __restrict__ sb,
        float* __restrict__ out) {
    __shared__ float s_dv[VDIM];
    __shared__ float s_half[2][DD];
    __shared__ int s_par[NN], s_cc[NN];
    __shared__ unsigned s_rm[4];
    __shared__ __align__(16) float s_m[2][2][DD][4];   // [chain warp][buf][d][c]

    int b = blockIdx.x, t = threadIdx.x;
    int wid = t >> 5, lane = t & 31;
    int k0 = lane * 4;

    // ===== phase 1: base embedding for node b =====
    {
        const float* vr = dv + (size_t)data[b] * VDIM;
        for (int i = t; i < VDIM; i += 256) s_dv[i] = vr[i];
        __syncthreads();
        int k = t & 127, half = t >> 7;
        float acc = 0.f;
        int vs = half * 150, ve = vs + 150;
#pragma unroll 10
        for (int v = vs; v < ve; v++) acc += s_dv[v] * __ldg(dw + v * DD + k);
        s_half[half][k] = acc;
        __syncthreads();
        if (t < DD) g_base[b * DD + t] = s_half[0][t] + s_half[1][t] + db[t];
        __syncthreads();
        if (t == 0) { __threadfence(); atomicAdd(&c_base[b], 1); }
    }

    // ===== phase 2: tree parse (CTAs 0..7) =====
    if (b < NG) {
        int g = b;
        if (t < NN) {
            int off = graphs[g * NN + t];
            bool isroot = (off == 0);
            int par = isroot ? -1 : ((t + off < NN) ? t + off : -1);
            unsigned bm = __ballot_sync(0xffffffffu, isroot);
            if (lane == 0) s_rm[wid] = bm;
            s_par[t] = par; s_cc[t] = 0;
        }
        __syncthreads();
        if (t == 0) {
            // faithful root chaining: effective parent of r_i = r_i + r_{i+1}
            int prev = -1;
            for (int q = 0; q < 4; q++) {
                unsigned mm = s_rm[q];
                while (mm) {
                    int bb = __ffs(mm) - 1; mm &= mm - 1;
                    int r = q * 32 + bb;
                    if (prev >= 0) { int p = prev + r; s_par[prev] = (p < NN) ? p : -1; }
                    prev = r;
                }
            }
            s_par[prev] = -1;   // final root
        }
        __syncthreads();
        if (t < NN) { int p = s_par[t]; if (p >= 0) atomicAdd(&s_cc[p], 1); }
        __syncthreads();
        if (t == 0) {
            int plen = 0, p = *posp;
            while (p >= 0) {
                g_plist[g][plen] = p;
                g_pedge[g][plen] = edges[p];
                plen++;
                p = s_par[p];
            }
            g_plen[g] = plen;
        }
        __syncthreads();
        if (t < NN) {
            g_par[g][t] = s_par[t];
            g_cc[g][t] = s_cc[t];
            g_inpath[g][t] = 0;
        }
        __syncthreads();
        if (t == 0) {
            int plen = g_plen[g];
            for (int i = 0; i < plen; i++) g_inpath[g][g_plist[g][i]] = 1;
            __threadfence();
            atomicAdd(&c_parse[g], 1);
        }
    }

    // ===== phase 3: dataflow vector pass, warp = (g, n) =====
    {
        int Wd = b * 8 + wid, g = Wd >> 7, n = Wd & 127;
        warp_spin_ge(&c_parse[g], 1);

        if (g_inpath[g][n]) {
            int plen = g_plen[g];
            int idx = 0;
            while (g_plist[g][idx] != n) idx++;
            if (idx == plen - 1) {                     // root: compute fold early
                if (plen > 1) {
                    int er = g_pedge[g][plen - 1];
                    float4 sv = *(const float4*)(sew + k0);
                    // w2[d] = sum_k W[d,k]*sew[k]  (ROW dots; lane owns rows k0..k0+3)
                    const float* Wb = ew + (size_t)er * (DD * DD);
                    float w20 = 0.f, w21 = 0.f, w22 = 0.f, w23 = 0.f;
#pragma unroll 4
                    for (int jq = 0; jq < 32; jq++) {
                        float s0 = __shfl_sync(0xffffffffu, sv.x, jq);
                        float s1 = __shfl_sync(0xffffffffu, sv.y, jq);
                        float s2 = __shfl_sync(0xffffffffu, sv.z, jq);
                        float s3 = __shfl_sync(0xffffffffu, sv.w, jq);
                        float4 r0 = __ldg((const float4*)(Wb + (k0 + 0) * DD + jq * 4));
                        float4 r1 = __ldg((const float4*)(Wb + (k0 + 1) * DD + jq * 4));
                        float4 r2 = __ldg((const float4*)(Wb + (k0 + 2) * DD + jq * 4));
                        float4 r3 = __ldg((const float4*)(Wb + (k0 + 3) * DD + jq * 4));
                        w20 += r0.x * s0 + r0.y * s1 + r0.z * s2 + r0.w * s3;
                        w21 += r1.x * s0 + r1.y * s1 + r1.z * s2 + r1.w * s3;
                        w22 += r2.x * s0 + r2.y * s1 + r2.z * s2 + r2.w * s3;
                        w23 += r3.x * s0 + r3.y * s1 + r3.z * s2 + r3.w * s3;
                    }
                    *(float4*)(&g_w2[g][0] + k0) = make_float4(w20, w21, w22, w23);
                    float4 sv2 = *(const float4*)(sew + k0);
                    float4 bb = *(const float4*)(ebias + er * DD + k0);
                    float cc = warp_red(bb.x * sv2.x + bb.y * sv2.y + bb.z * sv2.z + bb.w * sv2.w);
                    if (lane == 0) g_cconst[g] = cc;
                }
                __threadfence();
                if (lane == 0) atomicAdd(&c_fold[g], 1);
            }
            warp_spin_ge(&c_base[n], 1);
            float4 base4 = *(const float4*)(g_base + n * DD + k0);
            if (g == 0 && idx == 0) {                  // dscore (raw base[pos])
                float4 sd = *(const float4*)(sdw + k0);
                float p = warp_red(base4.x * sd.x + base4.y * sd.y + base4.z * sd.z + base4.w * sd.w);
                if (lane == 0) { g_dscore = p + sb[0]; __threadfence(); atomicAdd(&c_dscore, 1); }
            }
            int cc = g_cc[g][n];
            int tgt = cc - ((idx > 0) ? 1 : 0);        // path child does not signal
            float4 u = base4;
            if (tgt > 0) {
                warp_spin_ge(&g_cnt[g][n], tgt);
                float4 cs = __ldcg((const float4*)(&g_vacc[g][n * DD] + k0));
                u.x += cs.x; u.y += cs.y; u.z += cs.z; u.w += cs.w;
            }
            if (idx == 0 && cc > 0) {                  // v0 relu iff pos is internal
                u.x = fmaxf(u.x, 0.f); u.y = fmaxf(u.y, 0.f);
                u.z = fmaxf(u.z, 0.f); u.w = fmaxf(u.w, 0.f);
            }
            *(float4*)(&g_u[g][idx][0] + k0) = u;
            __threadfence(); __syncwarp();
            if (lane == 0) atomicAdd(&c_path[g], 1);
        } else {
            int par = g_par[g][n];
            int cc = g_cc[g][n];
            warp_spin_ge(&c_base[n], 1);
            float4 v = *(const float4*)(g_base + n * DD + k0);
            if (cc > 0) {
                warp_spin_ge(&g_cnt[g][n], cc);
                float4 cs = __ldcg((const float4*)(&g_vacc[g][n * DD] + k0));
                v.x = fmaxf(v.x + cs.x, 0.f); v.y = fmaxf(v.y + cs.y, 0.f);
                v.z = fmaxf(v.z + cs.z, 0.f); v.w = fmaxf(v.w + cs.w, 0.f);
            }
            if (par >= 0) {
                int e = edges[n];
                float4 y = *(const float4*)(ebias + e * DD + k0);
                y = mv_acc(ew + (size_t)e * (DD * DD), v, y);
                float* dst = &g_vacc[g][par * DD] + k0;
                atomicAdd(dst + 0, y.x); atomicAdd(dst + 1, y.y);
                atomicAdd(dst + 2, y.z); atomicAdd(dst + 3, y.w);
                __threadfence(); __syncwarp();
                if (lane == 0) atomicAdd(&g_cnt[g][par], 1);
            }
        }
    }

    // ===== phase 4: chains (warps 0,1 of each CTA; 4 chains per warp) =====
    if (wid < 2) {
        int unit = b * 2 + wid;
        int cg = unit >> 5, e0 = (unit & 31) * 4;

        warp_spin_ge(&c_parse[cg], 1);
        int plen = g_plen[cg];
        warp_spin_ge(&c_dscore, 1);
        warp_spin_ge(&c_fold[cg], 1);
        warp_spin_ge(&c_path[cg], plen);

        float4 v0 = *(const float4*)(&g_u[cg][0][0] + k0);
        float dsc = g_dscore;

        float4 y[4];
#pragma unroll
        for (int c = 0; c < 4; c++) {
            int e = e0 + c;
            y[c] = *(const float4*)(ebias + e * DD + k0);
            y[c] = mv_acc(ew + (size_t)e * (DD * DD), v0, y[c]);
        }

        if (plen == 1) {
            float4 sv = *(const float4*)(sew + k0);
#pragma unroll
            for (int c = 0; c < 4; c++) {
                float p = warp_red(y[c].x * sv.x + y[c].y * sv.y + y[c].z * sv.z + y[c].w * sv.w);
                if (lane == 0) out[cg * EE + e0 + c] = dsc + p;
            }
        } else {
            float4 u1 = *(const float4*)(&g_u[cg][1][0] + k0);
#pragma unroll
            for (int c = 0; c < 4; c++) {
                s_m[wid][0][k0 + 0][c] = fmaxf(y[c].x + u1.x, 0.f);
                s_m[wid][0][k0 + 1][c] = fmaxf(y[c].y + u1.y, 0.f);
                s_m[wid][0][k0 + 2][c] = fmaxf(y[c].z + u1.z, 0.f);
                s_m[wid][0][k0 + 3][c] = fmaxf(y[c].w + u1.w, 0.f);
            }
            __syncwarp();
            int cur = 0;
            for (int i = 2; i < plen; i++) {
                int eid = g_pedge[cg][i - 1];
                const float* W = ew + (size_t)eid * (DD * DD) + k0;
                float4 bv = *(const float4*)(ebias + eid * DD + k0);
                float a[4][4];
#pragma unroll
                for (int c = 0; c < 4; c++) {
                    a[c][0] = bv.x; a[c][1] = bv.y; a[c][2] = bv.z; a[c][3] = bv.w;
                }
#pragma unroll 8
                for (int d = 0; d < DD; d++) {
                    float4 wv = __ldg((const float4*)(W + d * DD));
                    float4 m4 = *(const float4*)&s_m[wid][cur][d][0];
                    a[0][0] += m4.x * wv.x; a[0][1] += m4.x * wv.y; a[0][2] += m4.x * wv.z; a[0][3] += m4.x * wv.w;
                    a[1][0] += m4.y * wv.x; a[1][1] += m4.y * wv.y; a[1][2] += m4.y * wv.z; a[1][3] += m4.y * wv.w;
                    a[2][0] += m4.z * wv.x; a[2][1] += m4.z * wv.y; a[2][2] += m4.z * wv.z; a[2][3] += m4.z * wv.w;
                    a[3][0] += m4.w * wv.x; a[3][1] += m4.w * wv.y; a[3][2] += m4.w * wv.z; a[3][3] += m4.w * wv.w;
                }
                float4 u4 = *(const float4*)(&g_u[cg][i][0] + k0);
                __syncwarp();
#pragma unroll
                for (int c = 0; c < 4; c++) {
                    s_m[wid][cur ^ 1][k0 + 0][c] = fmaxf(u4.x + a[c][0], 0.f);
                    s_m[wid][cur ^ 1][k0 + 1][c] = fmaxf(u4.y + a[c][1], 0.f);
                    s_m[wid][cur ^ 1][k0 + 2][c] = fmaxf(u4.z + a[c][2], 0.f);
                    s_m[wid][cur ^ 1][k0 + 3][c] = fmaxf(u4.w + a[c][3], 0.f);
                }
                __syncwarp();
                cur ^= 1;
            }
            float4 w2v = *(const float4*)(&g_w2[cg][0] + k0);
            float ccst = g_cconst[cg];
#pragma unroll
            for (int c = 0; c < 4; c++) {
                float p = s_m[wid][cur][k0 + 0][c] * w2v.x + s_m[wid][cur][k0 + 1][c] * w2v.y
                        + s_m[wid][cur][k0 + 2][c] * w2v.z + s_m[wid][cur][k0 + 3][c] * w2v.w;
                p = warp_red(p);
                if (lane == 0) out[cg * EE + e0 + c] = dsc + ccst + p;
            }
        }
    }
}

// =============== launcher ===============
extern "C" void kernel_launch(void* const* d_in, const int* in_sizes, int n_in,
                              void* d_out, int out_size) {
    const int*   data   = (const int*)d_in[0];
    const int*   graphs = (const int*)d_in[2];
    const int*   edges  = (const int*)d_in[3];
    const int*   pos    = (const int*)d_in[4];
    const float* dv     = (const float*)d_in[5];
    const float* dw     = (const float*)d_in[6];
    const float* db     = (const float*)d_in[7];
    const float* ew     = (const float*)d_in[8];
    const float* ebias  = (const float*)d_in[9];
    const float* sew    = (const float*)d_in[10];
    const float* sdw    = (const float*)d_in[11];
    const float* sb     = (const float*)d_in[12];
    float* out = (float*)d_out;

    k_reset<<<128, 256>>>();
    k_fused<<<128, 256>>>(data, graphs, edges, pos, dv, dw, db,
                          ew, ebias, sew, sdw, sb, out);
}

// round 10
// speedup vs baseline: 1.1306x; 1.1306x over previous
#include <cuda_runtime.h>
#include <cuda_bf16.h>
#include <cstdint>

#define NN   128
#define DD   128
#define EE   128
#define NG   8
#define VDIM 300

// ---------------- device scratch (allocation-free) ----------------
__device__ float g_base[NN * DD];
__device__ float g_vacc[NG][NN * DD];      // child-transform sums; zeroed by k_reset
__device__ float g_u[NG][NN][DD];          // path vectors, idx 0..plen-1 (idx0 = v0 w/ relu)
__device__ float g_w2[NG][DD];
__device__ float g_cconst[NG];
__device__ float g_dscore;
__device__ int   g_cnt[NG][NN];            // child-completion counters (warp granularity)
__device__ int   g_par[NG][NN];
__device__ int   g_cc[NG][NN];
__device__ unsigned char g_inpath[NG][NN];
__device__ int   g_plen[NG];
__device__ int   g_plist[NG][NN];
__device__ int   g_pedge[NG][NN];
// flags (zeroed by k_reset every launch)
__device__ int   c_parse[NG];
__device__ int   c_fold[NG];
__device__ int   c_path[NG];
__device__ int   c_base[NN];
__device__ int   c_dscore;

// =============== reset: runs first every launch; immune to dirty state ===============
__global__ void k_reset() {
    int i = blockIdx.x * blockDim.x + threadIdx.x;   // 0..32767
    ((float4*)g_vacc)[i] = make_float4(0.f, 0.f, 0.f, 0.f);
    if (i < NG) { c_parse[i] = 0; c_fold[i] = 0; c_path[i] = 0; }
    if (i < NN) c_base[i] = 0;
    if (i < NG * NN) ((int*)g_cnt)[i] = 0;
    if (i == 0) c_dscore = 0;
}

// ---------------- helpers ----------------
// Load-based poll: volatile L2 reads, NO atomic RMW (R9's 20x LTS-atomic
// oversubscription came from atomicAdd(p,0) polling).
__device__ __forceinline__ void warp_spin_ge(int* p, int tgt) {
    if ((threadIdx.x & 31) == 0) {
        volatile int* vp = (volatile int*)p;
        int backoff = 16;
        while (*vp < tgt) {
            __nanosleep(backoff);
            if (backoff < 512) backoff <<= 1;
        }
    }
    __syncwarp();
    __threadfence();
}

// y[k] += sum_d v[d] * W[d*DD + k]   (v @ W), v distributed float4/lane
__device__ __forceinline__ float4 mv_acc(const float* __restrict__ W, float4 vv, float4 y) {
    const float* Wl = W + (threadIdx.x & 31) * 4;
#pragma unroll 4
    for (int dq = 0; dq < 32; dq++) {
        float a0 = __shfl_sync(0xffffffffu, vv.x, dq);
        float a1 = __shfl_sync(0xffffffffu, vv.y, dq);
        float a2 = __shfl_sync(0xffffffffu, vv.z, dq);
        float a3 = __shfl_sync(0xffffffffu, vv.w, dq);
        float4 w0 = __ldg((const float4*)(Wl + (4 * dq + 0) * DD));
        float4 w1 = __ldg((const float4*)(Wl + (4 * dq + 1) * DD));
        float4 w2 = __ldg((const float4*)(Wl + (4 * dq + 2) * DD));
        float4 w3 = __ldg((const float4*)(Wl + (4 * dq + 3) * DD));
        y.x += a0 * w0.x + a1 * w1.x + a2 * w2.x + a3 * w3.x;
        y.y += a0 * w0.y + a1 * w1.y + a2 * w2.y + a3 * w3.y;
        y.z += a0 * w0.z + a1 * w1.z + a2 * w2.z + a3 * w3.z;
        y.w += a0 * w0.w + a1 * w1.w + a2 * w2.w + a3 * w3.w;
    }
    return y;
}

__device__ __forceinline__ float warp_red(float v) {
    for (int o = 16; o; o >>= 1) v += __shfl_xor_sync(0xffffffffu, v, o);
    return v;
}

// ---------------- the fused kernel ----------------
__global__ void __launch_bounds__(256, 1)
k_fused(const int* __restrict__ data, const int* __restrict__ graphs,
        const int* __restrict__ edges, const int* __restrict__ posp,
        const float* __restrict__ dv, const float* __restrict__ dw,
        const float* __restrict__ db, const float* __restrict__ ew,
        const float* __restrict__ ebias, const float* __restrict__ sew,
        const float* __restrict__ sdw, const float* __restrict__ sb,
        float* __restrict__ out) {
    __shared__ float s_dv[VDIM];
    __shared__ float s_half[2][DD];
    __shared__ int s_par[NN], s_cc[NN];
    __shared__ unsigned s_rm[4];
    __shared__ __align__(16) float s_m[4][2][DD][2];   // [chain warp][buf][d][c]

    int b = blockIdx.x, t = threadIdx.x;
    int wid = t >> 5, lane = t & 31;
    int k0 = lane * 4;

    // ===== phase 1: base embedding for node b =====
    {
        const float* vr = dv + (size_t)data[b] * VDIM;
        for (int i = t; i < VDIM; i += 256) s_dv[i] = vr[i];
        __syncthreads();
        int k = t & 127, half = t >> 7;
        float acc = 0.f;
        int vs = half * 150, ve = vs + 150;
#pragma unroll 10
        for (int v = vs; v < ve; v++) acc += s_dv[v] * __ldg(dw + v * DD + k);
        s_half[half][k] = acc;
        __syncthreads();
        if (t < DD) g_base[b * DD + t] = s_half[0][t] + s_half[1][t] + db[t];
        __syncthreads();
        if (t == 0) { __threadfence(); atomicAdd(&c_base[b], 1); }
    }

    // ===== phase 2: tree parse (CTAs 0..7) =====
    if (b < NG) {
        int g = b;
        if (t < NN) {
            int off = graphs[g * NN + t];
            bool isroot = (off == 0);
            int par = isroot ? -1 : ((t + off < NN) ? t + off : -1);
            unsigned bm = __ballot_sync(0xffffffffu, isroot);
            if (lane == 0) s_rm[wid] = bm;
            s_par[t] = par; s_cc[t] = 0;
        }
        __syncthreads();
        if (t == 0) {
            // faithful root chaining: effective parent of r_i = r_i + r_{i+1}
            int prev = -1;
            for (int q = 0; q < 4; q++) {
                unsigned mm = s_rm[q];
                while (mm) {
                    int bb = __ffs(mm) - 1; mm &= mm - 1;
                    int r = q * 32 + bb;
                    if (prev >= 0) { int p = prev + r; s_par[prev] = (p < NN) ? p : -1; }
                    prev = r;
                }
            }
            s_par[prev] = -1;   // final root
        }
        __syncthreads();
        if (t < NN) { int p = s_par[t]; if (p >= 0) atomicAdd(&s_cc[p], 1); }
        __syncthreads();
        if (t == 0) {
            int plen = 0, p = *posp;
            while (p >= 0) {
                g_plist[g][plen] = p;
                g_pedge[g][plen] = edges[p];
                plen++;
                p = s_par[p];
            }
            g_plen[g] = plen;
        }
        __syncthreads();
        if (t < NN) {
            g_par[g][t] = s_par[t];
            g_cc[g][t] = s_cc[t];
            g_inpath[g][t] = 0;
        }
        __syncthreads();
        if (t == 0) {
            int plen = g_plen[g];
            for (int i = 0; i < plen; i++) g_inpath[g][g_plist[g][i]] = 1;
            __threadfence();
            atomicAdd(&c_parse[g], 1);
        }
    }

    // ===== phase 3: dataflow vector pass, warp = (g, n) =====
    {
        int Wd = b * 8 + wid, g = Wd >> 7, n = Wd & 127;
        warp_spin_ge(&c_parse[g], 1);

        if (g_inpath[g][n]) {
            int plen = g_plen[g];
            int idx = 0;
            while (g_plist[g][idx] != n) idx++;
            if (idx == plen - 1) {                     // root: compute fold early
                if (plen > 1) {
                    int er = g_pedge[g][plen - 1];
                    float4 sv = *(const float4*)(sew + k0);
                    // w2[d] = sum_k W[d,k]*sew[k]  (ROW dots; lane owns rows k0..k0+3)
                    const float* Wb = ew + (size_t)er * (DD * DD);
                    float w20 = 0.f, w21 = 0.f, w22 = 0.f, w23 = 0.f;
#pragma unroll 4
                    for (int jq = 0; jq < 32; jq++) {
                        float s0 = __shfl_sync(0xffffffffu, sv.x, jq);
                        float s1 = __shfl_sync(0xffffffffu, sv.y, jq);
                        float s2 = __shfl_sync(0xffffffffu, sv.z, jq);
                        float s3 = __shfl_sync(0xffffffffu, sv.w, jq);
                        float4 r0 = __ldg((const float4*)(Wb + (k0 + 0) * DD + jq * 4));
                        float4 r1 = __ldg((const float4*)(Wb + (k0 + 1) * DD + jq * 4));
                        float4 r2 = __ldg((const float4*)(Wb + (k0 + 2) * DD + jq * 4));
                        float4 r3 = __ldg((const float4*)(Wb + (k0 + 3) * DD + jq * 4));
                        w20 += r0.x * s0 + r0.y * s1 + r0.z * s2 + r0.w * s3;
                        w21 += r1.x * s0 + r1.y * s1 + r1.z * s2 + r1.w * s3;
                        w22 += r2.x * s0 + r2.y * s1 + r2.z * s2 + r2.w * s3;
                        w23 += r3.x * s0 + r3.y * s1 + r3.z * s2 + r3.w * s3;
                    }
                    *(float4*)(&g_w2[g][0] + k0) = make_float4(w20, w21, w22, w23);
                    float4 sv2 = *(const float4*)(sew + k0);
                    float4 bb = *(const float4*)(ebias + er * DD + k0);
                    float cc = warp_red(bb.x * sv2.x + bb.y * sv2.y + bb.z * sv2.z + bb.w * sv2.w);
                    if (lane == 0) g_cconst[g] = cc;
                }
                __threadfence();
                if (lane == 0) atomicAdd(&c_fold[g], 1);
            }
            warp_spin_ge(&c_base[n], 1);
            float4 base4 = *(const float4*)(g_base + n * DD + k0);
            if (g == 0 && idx == 0) {                  // dscore (raw base[pos])
                float4 sd = *(const float4*)(sdw + k0);
                float p = warp_red(base4.x * sd.x + base4.y * sd.y + base4.z * sd.z + base4.w * sd.w);
                if (lane == 0) { g_dscore = p + sb[0]; __threadfence(); atomicAdd(&c_dscore, 1); }
            }
            int cc = g_cc[g][n];
            int tgt = cc - ((idx > 0) ? 1 : 0);        // path child does not signal
            float4 u = base4;
            if (tgt > 0) {
                warp_spin_ge(&g_cnt[g][n], tgt);
                float4 cs = __ldcg((const float4*)(&g_vacc[g][n * DD] + k0));
                u.x += cs.x; u.y += cs.y; u.z += cs.z; u.w += cs.w;
            }
            if (idx == 0 && cc > 0) {                  // v0 relu iff pos is internal
                u.x = fmaxf(u.x, 0.f); u.y = fmaxf(u.y, 0.f);
                u.z = fmaxf(u.z, 0.f); u.w = fmaxf(u.w, 0.f);
            }
            *(float4*)(&g_u[g][idx][0] + k0) = u;
            __threadfence(); __syncwarp();
            if (lane == 0) atomicAdd(&c_path[g], 1);
        } else {
            int par = g_par[g][n];
            int cc = g_cc[g][n];
            warp_spin_ge(&c_base[n], 1);
            float4 v = *(const float4*)(g_base + n * DD + k0);
            if (cc > 0) {
                warp_spin_ge(&g_cnt[g][n], cc);
                float4 cs = __ldcg((const float4*)(&g_vacc[g][n * DD] + k0));
                v.x = fmaxf(v.x + cs.x, 0.f); v.y = fmaxf(v.y + cs.y, 0.f);
                v.z = fmaxf(v.z + cs.z, 0.f); v.w = fmaxf(v.w + cs.w, 0.f);
            }
            if (par >= 0) {
                int e = edges[n];
                float4 y = *(const float4*)(ebias + e * DD + k0);
                y = mv_acc(ew + (size_t)e * (DD * DD), v, y);
                float* dst = &g_vacc[g][par * DD] + k0;
                atomicAdd(dst + 0, y.x); atomicAdd(dst + 1, y.y);
                atomicAdd(dst + 2, y.z); atomicAdd(dst + 3, y.w);
                __threadfence(); __syncwarp();
                if (lane == 0) atomicAdd(&g_cnt[g][par], 1);
            }
        }
    }

    // ===== phase 4: chains (warps 0..3 of each CTA; 2 chains per warp) =====
    if (wid < 4) {
        int unit = b * 4 + wid;                        // 0..511
        int cg = unit >> 6, e0 = (unit & 63) * 2;

        warp_spin_ge(&c_parse[cg], 1);
        int plen = g_plen[cg];
        warp_spin_ge(&c_dscore, 1);
        warp_spin_ge(&c_fold[cg], 1);
        warp_spin_ge(&c_path[cg], plen);

        float4 v0 = *(const float4*)(&g_u[cg][0][0] + k0);
        float dsc = g_dscore;

        float4 y[2];
#pragma unroll
        for (int c = 0; c < 2; c++) {
            int e = e0 + c;
            y[c] = *(const float4*)(ebias + e * DD + k0);
            y[c] = mv_acc(ew + (size_t)e * (DD * DD), v0, y[c]);
        }

        if (plen == 1) {
            float4 sv = *(const float4*)(sew + k0);
#pragma unroll
            for (int c = 0; c < 2; c++) {
                float p = warp_red(y[c].x * sv.x + y[c].y * sv.y + y[c].z * sv.z + y[c].w * sv.w);
                if (lane == 0) out[cg * EE + e0 + c] = dsc + p;
            }
        } else {
            float4 u1 = *(const float4*)(&g_u[cg][1][0] + k0);
#pragma unroll
            for (int c = 0; c < 2; c++) {
                s_m[wid][0][k0 + 0][c] = fmaxf(y[c].x + u1.x, 0.f);
                s_m[wid][0][k0 + 1][c] = fmaxf(y[c].y + u1.y, 0.f);
                s_m[wid][0][k0 + 2][c] = fmaxf(y[c].z + u1.z, 0.f);
                s_m[wid][0][k0 + 3][c] = fmaxf(y[c].w + u1.w, 0.f);
            }
            __syncwarp();
            int cur = 0;
            for (int i = 2; i < plen; i++) {
                int eid = g_pedge[cg][i - 1];
                const float* W = ew + (size_t)eid * (DD * DD) + k0;
                float4 bv = *(const float4*)(ebias + eid * DD + k0);
                float a[2][4];
#pragma unroll
                for (int c = 0; c < 2; c++) {
                    a[c][0] = bv.x; a[c][1] = bv.y; a[c][2] = bv.z; a[c][3] = bv.w;
                }
#pragma unroll 16
                for (int d = 0; d < DD; d++) {
                    float4 wv = __ldg((const float4*)(W + d * DD));
                    float2 m2 = *(const float2*)&s_m[wid][cur][d][0];
                    a[0][0] += m2.x * wv.x; a[0][1] += m2.x * wv.y; a[0][2] += m2.x * wv.z; a[0][3] += m2.x * wv.w;
                    a[1][0] += m2.y * wv.x; a[1][1] += m2.y * wv.y; a[1][2] += m2.y * wv.z; a[1][3] += m2.y * wv.w;
                }
                float4 u4 = *(const float4*)(&g_u[cg][i][0] + k0);
                __syncwarp();
#pragma unroll
                for (int c = 0; c < 2; c++) {
                    s_m[wid][cur ^ 1][k0 + 0][c] = fmaxf(u4.x + a[c][0], 0.f);
                    s_m[wid][cur ^ 1][k0 + 1][c] = fmaxf(u4.y + a[c][1], 0.f);
                    s_m[wid][cur ^ 1][k0 + 2][c] = fmaxf(u4.z + a[c][2], 0.f);
                    s_m[wid][cur ^ 1][k0 + 3][c] = fmaxf(u4.w + a[c][3], 0.f);
                }
                __syncwarp();
                cur ^= 1;
            }
            float4 w2v = *(const float4*)(&g_w2[cg][0] + k0);
            float ccst = g_cconst[cg];
#pragma unroll
            for (int c = 0; c < 2; c++) {
                float p = s_m[wid][cur][k0 + 0][c] * w2v.x + s_m[wid][cur][k0 + 1][c] * w2v.y
                        + s_m[wid][cur][k0 + 2][c] * w2v.z + s_m[wid][cur][k0 + 3][c] * w2v.w;
                p = warp_red(p);
                if (lane == 0) out[cg * EE + e0 + c] = dsc + ccst + p;
            }
        }
    }
}

// =============== launcher ===============
extern "C" void kernel_launch(void* const* d_in, const int* in_sizes, int n_in,
                              void* d_out, int out_size) {
    const int*   data   = (const int*)d_in[0];
    const int*   graphs = (const int*)d_in[2];
    const int*   edges  = (const int*)d_in[3];
    const int*   pos    = (const int*)d_in[4];
    const float* dv     = (const float*)d_in[5];
    const float* dw     = (const float*)d_in[6];
    const float* db     = (const float*)d_in[7];
    const float* ew     = (const float*)d_in[8];
    const float* ebias  = (const float*)d_in[9];
    const float* sew    = (const float*)d_in[10];
    const float* sdw    = (const float*)d_in[11];
    const float* sb     = (const float*)d_in[12];
    float* out = (float*)d_out;

    k_reset<<<128, 256>>>();
    k_fused<<<128, 256>>>(data, graphs, edges, pos, dv, dw, db,
                          ew, ebias, sew, sdw, sb, out);
}

// round 11
// speedup vs baseline: 1.1451x; 1.0128x over previous
#include <cuda_runtime.h>
#include <cuda_bf16.h>
#include <cstdint>

#define NN   128
#define DD   128
#define EE   128
#define NG   8
#define VDIM 300

// ---------------- device scratch (allocation-free) ----------------
__device__ float g_base[NN * DD];
__device__ float g_vacc[NG][NN * DD];      // child-transform sums; zeroed by k_reset
__device__ float g_u[NG][NN][DD];          // path vectors, idx 0..plen-1 (idx0 = v0 w/ relu)
__device__ float g_w2[NG][DD];
__device__ float g_cconst[NG];
__device__ float g_dscore;
__device__ int   g_cnt[NG][NN];            // child-completion counters (warp granularity)
__device__ int   g_par[NG][NN];
__device__ int   g_cc[NG][NN];
__device__ unsigned char g_inpath[NG][NN];
__device__ int   g_plen[NG];
__device__ int   g_plist[NG][NN];
__device__ int   g_pedge[NG][NN];
// flags (zeroed by k_reset every launch)
__device__ int   c_parse[NG];
__device__ int   c_fold[NG];
__device__ int   c_path[NG];
__device__ int   c_base[NN];
__device__ int   c_dscore;

// =============== reset: runs first every launch; immune to dirty state ===============
__global__ void k_reset() {
    int i = blockIdx.x * blockDim.x + threadIdx.x;   // 0..32767
    ((float4*)g_vacc)[i] = make_float4(0.f, 0.f, 0.f, 0.f);
    if (i < NG) { c_parse[i] = 0; c_fold[i] = 0; c_path[i] = 0; }
    if (i < NN) c_base[i] = 0;
    if (i < NG * NN) ((int*)g_cnt)[i] = 0;
    if (i == 0) c_dscore = 0;
}

// ---------------- helpers ----------------
// Tight volatile-load poll: NO __nanosleep (coarse sleep quantum was the R9/R10
// killer), NO atomic RMW (LTS serialization). L2 read latency self-throttles.
__device__ __forceinline__ void warp_spin_ge(int* p, int tgt) {
    if ((threadIdx.x & 31) == 0) {
        volatile int* vp = (volatile int*)p;
        while (*vp < tgt) { }
    }
    __syncwarp();
    __threadfence();
}

// y[k] += sum_d v[d] * W[d*DD + k]   (v @ W), v distributed float4/lane
__device__ __forceinline__ float4 mv_acc(const float* __restrict__ W, float4 vv, float4 y) {
    const float* Wl = W + (threadIdx.x & 31) * 4;
#pragma unroll 4
    for (int dq = 0; dq < 32; dq++) {
        float a0 = __shfl_sync(0xffffffffu, vv.x, dq);
        float a1 = __shfl_sync(0xffffffffu, vv.y, dq);
        float a2 = __shfl_sync(0xffffffffu, vv.z, dq);
        float a3 = __shfl_sync(0xffffffffu, vv.w, dq);
        float4 w0 = __ldg((const float4*)(Wl + (4 * dq + 0) * DD));
        float4 w1 = __ldg((const float4*)(Wl + (4 * dq + 1) * DD));
        float4 w2 = __ldg((const float4*)(Wl + (4 * dq + 2) * DD));
        float4 w3 = __ldg((const float4*)(Wl + (4 * dq + 3) * DD));
        y.x += a0 * w0.x + a1 * w1.x + a2 * w2.x + a3 * w3.x;
        y.y += a0 * w0.y + a1 * w1.y + a2 * w2.y + a3 * w3.y;
        y.z += a0 * w0.z + a1 * w1.z + a2 * w2.z + a3 * w3.z;
        y.w += a0 * w0.w + a1 * w1.w + a2 * w2.w + a3 * w3.w;
    }
    return y;
}

__device__ __forceinline__ float warp_red(float v) {
    for (int o = 16; o; o >>= 1) v += __shfl_xor_sync(0xffffffffu, v, o);
    return v;
}

// ---------------- the fused kernel ----------------
__global__ void __launch_bounds__(256, 1)
k_fused(const int* __restrict__ data, const int* __restrict__ graphs,
        const int* __restrict__ edges, const int* __restrict__ posp,
        const float* __restrict__ dv, const float* __restrict__ dw,
        const float* __restrict__ db, const float* __restrict__ ew,
        const float* __restrict__ ebias, const float* __restrict__ sew,
        const float* __restrict__ sdw, const float* __restrict__ sb,
        float* __restrict__ out) {
    __shared__ float s_dv[VDIM];
    __shared__ float s_half[2][DD];
    __shared__ int s_par[NN], s_cc[NN];
    __shared__ unsigned s_rm[4];
    __shared__ __align__(16) float s_m[4][2][DD][2];   // [chain warp][buf][d][c]

    int b = blockIdx.x, t = threadIdx.x;
    int wid = t >> 5, lane = t & 31;
    int k0 = lane * 4;

    // ===== phase 1: base embedding for node b =====
    {
        const float* vr = dv + (size_t)data[b] * VDIM;
        for (int i = t; i < VDIM; i += 256) s_dv[i] = vr[i];
        __syncthreads();
        int k = t & 127, half = t >> 7;
        float acc = 0.f;
        int vs = half * 150, ve = vs + 150;
#pragma unroll 10
        for (int v = vs; v < ve; v++) acc += s_dv[v] * __ldg(dw + v * DD + k);
        s_half[half][k] = acc;
        __syncthreads();
        if (t < DD) g_base[b * DD + t] = s_half[0][t] + s_half[1][t] + db[t];
        __syncthreads();
        if (t == 0) { __threadfence(); atomicAdd(&c_base[b], 1); }
    }

    // ===== phase 2: tree parse (CTAs 0..7) =====
    if (b < NG) {
        int g = b;
        if (t < NN) {
            int off = graphs[g * NN + t];
            bool isroot = (off == 0);
            int par = isroot ? -1 : ((t + off < NN) ? t + off : -1);
            unsigned bm = __ballot_sync(0xffffffffu, isroot);
            if (lane == 0) s_rm[wid] = bm;
            s_par[t] = par; s_cc[t] = 0;
        }
        __syncthreads();
        if (t == 0) {
            // faithful root chaining: effective parent of r_i = r_i + r_{i+1}
            int prev = -1;
            for (int q = 0; q < 4; q++) {
                unsigned mm = s_rm[q];
                while (mm) {
                    int bb = __ffs(mm) - 1; mm &= mm - 1;
                    int r = q * 32 + bb;
                    if (prev >= 0) { int p = prev + r; s_par[prev] = (p < NN) ? p : -1; }
                    prev = r;
                }
            }
            s_par[prev] = -1;   // final root
        }
        __syncthreads();
        if (t < NN) { int p = s_par[t]; if (p >= 0) atomicAdd(&s_cc[p], 1); }
        __syncthreads();
        if (t == 0) {
            int plen = 0, p = *posp;
            while (p >= 0) {
                g_plist[g][plen] = p;
                g_pedge[g][plen] = edges[p];
                plen++;
                p = s_par[p];
            }
            g_plen[g] = plen;
        }
        __syncthreads();
        if (t < NN) {
            g_par[g][t] = s_par[t];
            g_cc[g][t] = s_cc[t];
            g_inpath[g][t] = 0;
        }
        __syncthreads();
        if (t == 0) {
            int plen = g_plen[g];
            for (int i = 0; i < plen; i++) g_inpath[g][g_plist[g][i]] = 1;
            __threadfence();
            atomicAdd(&c_parse[g], 1);
        }
    }

    // ===== phase 3: dataflow vector pass, warp = (g, n) =====
    {
        int Wd = b * 8 + wid, g = Wd >> 7, n = Wd & 127;
        warp_spin_ge(&c_parse[g], 1);

        if (g_inpath[g][n]) {
            int plen = g_plen[g];
            int idx = 0;
            while (g_plist[g][idx] != n) idx++;
            if (idx == plen - 1) {                     // root: compute fold early
                if (plen > 1) {
                    int er = g_pedge[g][plen - 1];
                    float4 sv = *(const float4*)(sew + k0);
                    // w2[d] = sum_k W[d,k]*sew[k]  (ROW dots; lane owns rows k0..k0+3)
                    const float* Wb = ew + (size_t)er * (DD * DD);
                    float w20 = 0.f, w21 = 0.f, w22 = 0.f, w23 = 0.f;
#pragma unroll 4
                    for (int jq = 0; jq < 32; jq++) {
                        float s0 = __shfl_sync(0xffffffffu, sv.x, jq);
                        float s1 = __shfl_sync(0xffffffffu, sv.y, jq);
                        float s2 = __shfl_sync(0xffffffffu, sv.z, jq);
                        float s3 = __shfl_sync(0xffffffffu, sv.w, jq);
                        float4 r0 = __ldg((const float4*)(Wb + (k0 + 0) * DD + jq * 4));
                        float4 r1 = __ldg((const float4*)(Wb + (k0 + 1) * DD + jq * 4));
                        float4 r2 = __ldg((const float4*)(Wb + (k0 + 2) * DD + jq * 4));
                        float4 r3 = __ldg((const float4*)(Wb + (k0 + 3) * DD + jq * 4));
                        w20 += r0.x * s0 + r0.y * s1 + r0.z * s2 + r0.w * s3;
                        w21 += r1.x * s0 + r1.y * s1 + r1.z * s2 + r1.w * s3;
                        w22 += r2.x * s0 + r2.y * s1 + r2.z * s2 + r2.w * s3;
                        w23 += r3.x * s0 + r3.y * s1 + r3.z * s2 + r3.w * s3;
                    }
                    *(float4*)(&g_w2[g][0] + k0) = make_float4(w20, w21, w22, w23);
                    float4 sv2 = *(const float4*)(sew + k0);
                    float4 bb = *(const float4*)(ebias + er * DD + k0);
                    float cc = warp_red(bb.x * sv2.x + bb.y * sv2.y + bb.z * sv2.z + bb.w * sv2.w);
                    if (lane == 0) g_cconst[g] = cc;
                }
                __threadfence();
                if (lane == 0) atomicAdd(&c_fold[g], 1);
            }
            warp_spin_ge(&c_base[n], 1);
            float4 base4 = *(const float4*)(g_base + n * DD + k0);
            if (g == 0 && idx == 0) {                  // dscore (raw base[pos])
                float4 sd = *(const float4*)(sdw + k0);
                float p = warp_red(base4.x * sd.x + base4.y * sd.y + base4.z * sd.z + base4.w * sd.w);
                if (lane == 0) { g_dscore = p + sb[0]; __threadfence(); atomicAdd(&c_dscore, 1); }
            }
            int cc = g_cc[g][n];
            int tgt = cc - ((idx > 0) ? 1 : 0);        // path child does not signal
            float4 u = base4;
            if (tgt > 0) {
                warp_spin_ge(&g_cnt[g][n], tgt);
                float4 cs = __ldcg((const float4*)(&g_vacc[g][n * DD] + k0));
                u.x += cs.x; u.y += cs.y; u.z += cs.z; u.w += cs.w;
            }
            if (idx == 0 && cc > 0) {                  // v0 relu iff pos is internal
                u.x = fmaxf(u.x, 0.f); u.y = fmaxf(u.y, 0.f);
                u.z = fmaxf(u.z, 0.f); u.w = fmaxf(u.w, 0.f);
            }
            *(float4*)(&g_u[g][idx][0] + k0) = u;
            __threadfence(); __syncwarp();
            if (lane == 0) atomicAdd(&c_path[g], 1);
        } else {
            int par = g_par[g][n];
            int cc = g_cc[g][n];
            warp_spin_ge(&c_base[n], 1);
            float4 v = *(const float4*)(g_base + n * DD + k0);
            if (cc > 0) {
                warp_spin_ge(&g_cnt[g][n], cc);
                float4 cs = __ldcg((const float4*)(&g_vacc[g][n * DD] + k0));
                v.x = fmaxf(v.x + cs.x, 0.f); v.y = fmaxf(v.y + cs.y, 0.f);
                v.z = fmaxf(v.z + cs.z, 0.f); v.w = fmaxf(v.w + cs.w, 0.f);
            }
            if (par >= 0) {
                int e = edges[n];
                float4 y = *(const float4*)(ebias + e * DD + k0);
                y = mv_acc(ew + (size_t)e * (DD * DD), v, y);
                float* dst = &g_vacc[g][par * DD] + k0;
                atomicAdd(dst + 0, y.x); atomicAdd(dst + 1, y.y);
                atomicAdd(dst + 2, y.z); atomicAdd(dst + 3, y.w);
                __threadfence(); __syncwarp();
                if (lane == 0) atomicAdd(&g_cnt[g][par], 1);
            }
        }
    }

    // ===== phase 4: chains (warps 0..3 of each CTA; 2 chains per warp) =====
    if (wid < 4) {
        int unit = b * 4 + wid;                        // 0..511
        int cg = unit >> 6, e0 = (unit & 63) * 2;

        warp_spin_ge(&c_parse[cg], 1);
        int plen = g_plen[cg];
        warp_spin_ge(&c_dscore, 1);
        warp_spin_ge(&c_fold[cg], 1);
        warp_spin_ge(&c_path[cg], plen);

        float4 v0 = *(const float4*)(&g_u[cg][0][0] + k0);
        float dsc = g_dscore;

        float4 y[2];
#pragma unroll
        for (int c = 0; c < 2; c++) {
            int e = e0 + c;
            y[c] = *(const float4*)(ebias + e * DD + k0);
            y[c] = mv_acc(ew + (size_t)e * (DD * DD), v0, y[c]);
        }

        if (plen == 1) {
            float4 sv = *(const float4*)(sew + k0);
#pragma unroll
            for (int c = 0; c < 2; c++) {
                float p = warp_red(y[c].x * sv.x + y[c].y * sv.y + y[c].z * sv.z + y[c].w * sv.w);
                if (lane == 0) out[cg * EE + e0 + c] = dsc + p;
            }
        } else {
            float4 u1 = *(const float4*)(&g_u[cg][1][0] + k0);
#pragma unroll
            for (int c = 0; c < 2; c++) {
                s_m[wid][0][k0 + 0][c] = fmaxf(y[c].x + u1.x, 0.f);
                s_m[wid][0][k0 + 1][c] = fmaxf(y[c].y + u1.y, 0.f);
                s_m[wid][0][k0 + 2][c] = fmaxf(y[c].z + u1.z, 0.f);
                s_m[wid][0][k0 + 3][c] = fmaxf(y[c].w + u1.w, 0.f);
            }
            __syncwarp();
            int cur = 0;
            for (int i = 2; i < plen; i++) {
                int eid = g_pedge[cg][i - 1];
                const float* W = ew + (size_t)eid * (DD * DD) + k0;
                float4 bv = *(const float4*)(ebias + eid * DD + k0);
                float a[2][4];
#pragma unroll
                for (int c = 0; c < 2; c++) {
                    a[c][0] = bv.x; a[c][1] = bv.y; a[c][2] = bv.z; a[c][3] = bv.w;
                }
#pragma unroll 16
                for (int d = 0; d < DD; d++) {
                    float4 wv = __ldg((const float4*)(W + d * DD));
                    float2 m2 = *(const float2*)&s_m[wid][cur][d][0];
                    a[0][0] += m2.x * wv.x; a[0][1] += m2.x * wv.y; a[0][2] += m2.x * wv.z; a[0][3] += m2.x * wv.w;
                    a[1][0] += m2.y * wv.x; a[1][1] += m2.y * wv.y; a[1][2] += m2.y * wv.z; a[1][3] += m2.y * wv.w;
                }
                float4 u4 = *(const float4*)(&g_u[cg][i][0] + k0);
                __syncwarp();
#pragma unroll
                for (int c = 0; c < 2; c++) {
                    s_m[wid][cur ^ 1][k0 + 0][c] = fmaxf(u4.x + a[c][0], 0.f);
                    s_m[wid][cur ^ 1][k0 + 1][c] = fmaxf(u4.y + a[c][1], 0.f);
                    s_m[wid][cur ^ 1][k0 + 2][c] = fmaxf(u4.z + a[c][2], 0.f);
                    s_m[wid][cur ^ 1][k0 + 3][c] = fmaxf(u4.w + a[c][3], 0.f);
                }
                __syncwarp();
                cur ^= 1;
            }
            float4 w2v = *(const float4*)(&g_w2[cg][0] + k0);
            float ccst = g_cconst[cg];
#pragma unroll
            for (int c = 0; c < 2; c++) {
                float p = s_m[wid][cur][k0 + 0][c] * w2v.x + s_m[wid][cur][k0 + 1][c] * w2v.y
                        + s_m[wid][cur][k0 + 2][c] * w2v.z + s_m[wid][cur][k0 + 3][c] * w2v.w;
                p = warp_red(p);
                if (lane == 0) out[cg * EE + e0 + c] = dsc + ccst + p;
            }
        }
    }
}

// =============== launcher ===============
extern "C" void kernel_launch(void* const* d_in, const int* in_sizes, int n_in,
                              void* d_out, int out_size) {
    const int*   data   = (const int*)d_in[0];
    const int*   graphs = (const int*)d_in[2];
    const int*   edges  = (const int*)d_in[3];
    const int*   pos    = (const int*)d_in[4];
    const float* dv     = (const float*)d_in[5];
    const float* dw     = (const float*)d_in[6];
    const float* db     = (const float*)d_in[7];
    const float* ew     = (const float*)d_in[8];
    const float* ebias  = (const float*)d_in[9];
    const float* sew    = (const float*)d_in[10];
    const float* sdw    = (const float*)d_in[11];
    const float* sb     = (const float*)d_in[12];
    float* out = (float*)d_out;

    k_reset<<<128, 256>>>();
    k_fused<<<128, 256>>>(data, graphs, edges, pos, dv, dw, db,
                          ew, ebias, sew, sdw, sb, out);
}